// round 6
// baseline (speedup 1.0000x reference)
#include <cuda_runtime.h>
#include <cstdint>

#define Bq 8
#define Hq 128
#define Wq 128
#define Cq 128
#define Fq 128

// ---------------------------------------------------------------------------
// Modulated+demodulated weights in MMA-friendly layout:
//   g_wmod[((b*9 + tap)*4 + cc)*4096 + kk*128 + f]   (kk = c%32, cc = c/32)
// Values pre-rounded to tf32 (cvt.rna).
// ---------------------------------------------------------------------------
__device__ float g_wmod[Bq * 9 * Cq * Fq];

__global__ __launch_bounds__(256) void modw_kernel(const float* __restrict__ style,
                                                   const float* __restrict__ kern)
{
    const int fg = blockIdx.x;
    const int b  = blockIdx.y;
    const int f0 = fg * 32;
    const int tid = threadIdx.x;
    const int fi = tid & 31;
    const int cp = tid >> 5;

    __shared__ float ssty[Cq];
    __shared__ float red[8][32];
    __shared__ float rr[32];

    if (tid < Cq) ssty[tid] = style[b * Cq + tid] + 1.0f;
    __syncthreads();

    float sq = 0.0f;
    for (int k = 0; k < 9; k++) {
#pragma unroll 4
        for (int j = 0; j < 16; j++) {
            int c = cp + j * 8;
            float kv = kern[(k * Cq + c) * Fq + f0 + fi] * ssty[c];
            sq += kv * kv;
        }
    }
    red[cp][fi] = sq;
    __syncthreads();
    if (tid < 32) {
        float t = 0.0f;
#pragma unroll
        for (int j = 0; j < 8; j++) t += red[j][tid];
        float xarg = t + 1e-8f;
        float r = rsqrtf(xarg);
        r = r * (1.5f - 0.5f * xarg * r * r);
        rr[tid] = r;
    }
    __syncthreads();

    for (int i = tid; i < 9 * Cq * 32; i += 256) {
        int k   = i >> 12;
        int rem = i & 4095;
        int c   = rem >> 5;
        int fl  = rem & 31;
        float v = kern[(k * Cq + c) * Fq + f0 + fl] * ssty[c] * rr[fl];
        uint32_t bits;
        asm("cvt.rna.tf32.f32 %0, %1;" : "=r"(bits) : "f"(v));
        g_wmod[(((b * 9 + k) * 4 + (c >> 5)) * 32 + (c & 31)) * Fq + f0 + fl] =
            __uint_as_float(bits);
    }
}

// ---------------------------------------------------------------------------
// Conv kernel: CTA = (b, output row h0). GEMM M=128(w) x N=128(f), K=1152.
// mma.sync.m16n8k8 tf32.  16 warps = 4(m) x 4(n), warp tile 32x32.
// ---------------------------------------------------------------------------
#define XS_WORDS 12480                 // 3 rows * 130 pos * 32 c floats
#define WS_WORDS 4096                  // 32 k * 128 f floats
#define SMEM_WORDS (2 * XS_WORDS + 2 * WS_WORDS)
#define SMEM_BYTES (SMEM_WORDS * 4)    // 132608

#define NTHREADS 512

__device__ __forceinline__ void cp_async16(uint32_t daddr, const void* saddr, int srcsz) {
    asm volatile("cp.async.cg.shared.global [%0], [%1], 16, %2;"
                 :: "r"(daddr), "l"(saddr), "r"(srcsz) : "memory");
}
__device__ __forceinline__ void cp_commit() {
    asm volatile("cp.async.commit_group;" ::: "memory");
}
__device__ __forceinline__ void cp_wait1() {
    asm volatile("cp.async.wait_group 1;" ::: "memory");
}

__device__ __forceinline__ void mma_tf32(float& c0, float& c1, float& c2, float& c3,
                                         uint32_t a0, uint32_t a1, uint32_t a2, uint32_t a3,
                                         uint32_t b0, uint32_t b1) {
    asm volatile("mma.sync.aligned.m16n8k8.row.col.f32.tf32.tf32.f32 "
                 "{%0,%1,%2,%3}, {%4,%5,%6,%7}, {%8,%9}, {%0,%1,%2,%3};"
                 : "+f"(c0), "+f"(c1), "+f"(c2), "+f"(c3)
                 : "r"(a0), "r"(a1), "r"(a2), "r"(a3), "r"(b0), "r"(b1));
}

__global__ __launch_bounds__(NTHREADS, 1) void conv_tc_kernel(const float* __restrict__ x,
                                                              float* __restrict__ out)
{
    extern __shared__ float sm[];
    uint32_t smbase;
    asm("{ .reg .u64 t; cvta.to.shared.u64 t, %1; cvt.u32.u64 %0, t; }"
        : "=r"(smbase) : "l"(sm));

    const int tid = threadIdx.x;
    const int lane = tid & 31;
    const int wid  = tid >> 5;
    const int g    = lane >> 2;       // groupID (0..7)
    const int tig  = lane & 3;        // thread-in-group
    const int warpM = wid & 3;        // 0..3 (m tiles of 32)
    const int warpN = wid >> 2;       // 0..3 (n tiles of 32)

    const int h0 = blockIdx.x;
    const int b  = blockIdx.y;

    float acc[2][4][4];
#pragma unroll
    for (int mt = 0; mt < 2; mt++)
#pragma unroll
        for (int nt = 0; nt < 4; nt++)
#pragma unroll
            for (int q = 0; q < 4; q++) acc[mt][nt][q] = 0.0f;

    // x band for c-chunk cc into buffer bb: xs[r][p][kk], word swizzle kk ^ ((p&7)*4)
    auto fill_band = [&](int cc, int bb) {
        const float* xb = x + ((size_t)b * Hq) * Wq * Cq + cc * 32;
        for (int i = tid; i < 3 * 130 * 8; i += NTHREADS) {
            int r   = i / 1040;
            int rem = i - r * 1040;
            int p   = rem >> 3;
            int kk4 = rem & 7;
            int gh = h0 - 1 + r;
            int gw = p - 1;
            int valid = (gh >= 0 && gh < Hq && gw >= 0 && gw < Wq) ? 16 : 0;
            int ghc = gh < 0 ? 0 : (gh > Hq - 1 ? Hq - 1 : gh);
            int gwc = gw < 0 ? 0 : (gw > Wq - 1 ? Wq - 1 : gw);
            const float* src = xb + ((size_t)ghc * Wq + gwc) * Cq + kk4 * 4;
            uint32_t w = bb * XS_WORDS + (r * 130 + p) * 32 + ((kk4 * 4) ^ ((p & 7) * 4));
            cp_async16(smbase + w * 4, src, valid);
        }
    };
    // weight slab (b,tap,cc) into buffer bb: ws[k][f], word swizzle f ^ ((k&3)*8)
    auto fill_ws = [&](int tap, int cc, int bb) {
        const float* src0 = g_wmod + (((size_t)(b * 9 + tap) * 4 + cc)) * 4096;
        for (int i = tid; i < 1024; i += NTHREADS) {
            int kk = i >> 5;
            int f4 = i & 31;
            uint32_t w = 2 * XS_WORDS + bb * WS_WORDS + kk * 128 + ((f4 * 4) ^ ((kk & 3) * 8));
            cp_async16(smbase + w * 4, src0 + kk * 128 + f4 * 4, 16);
        }
    };

    // ---- prologue ----
    fill_band(0, 0);
    fill_ws(0, 0, 0);
    cp_commit();

    for (int it = 0; it < 36; it++) {
        const int cc  = it / 9;
        const int tap = it - cc * 9;
        const int kh = tap / 3;
        const int kw = tap - kh * 3;

        __syncthreads();            // prev iter's reads of prefetch buffers done
        if (it + 1 < 36) {
            int itn = it + 1;
            int ccn = itn / 9;
            fill_ws(itn - ccn * 9, ccn, itn & 1);
            if (tap == 0 && cc + 1 < 4) fill_band(cc + 1, (cc + 1) & 1);
        }
        cp_commit();
        cp_wait1();                 // ws(it) + band(cc) ready
        __syncthreads();

        const int xb = (cc & 1) * XS_WORDS + kh * 130 * 32;
        const int wb = 2 * XS_WORDS + (it & 1) * WS_WORDS;

        const int mA = warpM * 32 + g;          // mt0 rows g, g+8
        const int mB = mA + 16;                 // mt1 rows
        const int pA0 = mA + kw,  pA1 = pA0 + 8;
        const int pB0 = mB + kw,  pB1 = pB0 + 8;
        const int baseA0 = xb + pA0 * 32, mkA0 = (pA0 & 7) * 4;
        const int baseA1 = xb + pA1 * 32, mkA1 = (pA1 & 7) * 4;
        const int baseB0 = xb + pB0 * 32, mkB0 = (pB0 & 7) * 4;
        const int baseB1 = xb + pB1 * 32, mkB1 = (pB1 & 7) * 4;

#pragma unroll
        for (int ks = 0; ks < 4; ks++) {
            const int k0 = ks * 8 + tig;
            uint32_t a0[2], a1[2], a2[2], a3[2];
            a0[0] = __float_as_uint(sm[baseA0 + (k0 ^ mkA0)]);
            a2[0] = __float_as_uint(sm[baseA0 + ((k0 + 4) ^ mkA0)]);
            a1[0] = __float_as_uint(sm[baseA1 + (k0 ^ mkA1)]);
            a3[0] = __float_as_uint(sm[baseA1 + ((k0 + 4) ^ mkA1)]);
            a0[1] = __float_as_uint(sm[baseB0 + (k0 ^ mkB0)]);
            a2[1] = __float_as_uint(sm[baseB0 + ((k0 + 4) ^ mkB0)]);
            a1[1] = __float_as_uint(sm[baseB1 + (k0 ^ mkB1)]);
            a3[1] = __float_as_uint(sm[baseB1 + ((k0 + 4) ^ mkB1)]);

            const int brow = wb + k0 * 128;
#pragma unroll
            for (int nt = 0; nt < 4; nt++) {
                uint32_t bw = brow + (((warpN * 32 + nt * 8 + g) ^ (tig * 8)));
                uint32_t b0 = __float_as_uint(sm[bw]);
                uint32_t b1 = __float_as_uint(sm[bw + 512]);
                mma_tf32(acc[0][nt][0], acc[0][nt][1], acc[0][nt][2], acc[0][nt][3],
                         a0[0], a1[0], a2[0], a3[0], b0, b1);
                mma_tf32(acc[1][nt][0], acc[1][nt][1], acc[1][nt][2], acc[1][nt][3],
                         a0[1], a1[1], a2[1], a3[1], b0, b1);
            }
        }
    }

    // ---- epilogue: direct STG from accumulators ----
    float* ob = out + (((size_t)b * Hq + h0) * Wq) * Fq;
#pragma unroll
    for (int mt = 0; mt < 2; mt++) {
        const int m = warpM * 32 + mt * 16 + g;
#pragma unroll
        for (int nt = 0; nt < 4; nt++) {
            const int f = warpN * 32 + nt * 8 + tig * 2;
            float2 v0 = make_float2(acc[mt][nt][0], acc[mt][nt][1]);
            float2 v1 = make_float2(acc[mt][nt][2], acc[mt][nt][3]);
            *(float2*)(ob + (size_t)m * Fq + f) = v0;
            *(float2*)(ob + (size_t)(m + 8) * Fq + f) = v1;
        }
    }
}

// ---------------------------------------------------------------------------
extern "C" void kernel_launch(void* const* d_in, const int* in_sizes, int n_in,
                              void* d_out, int out_size)
{
    const float* x     = (const float*)d_in[0];   // (8,128,128,128) NHWC
    const float* style = (const float*)d_in[1];   // (8,128)
    const float* kern  = (const float*)d_in[2];   // (3,3,128,128)
    float* out = (float*)d_out;

    (void)in_sizes; (void)n_in; (void)out_size;

    cudaFuncSetAttribute(conv_tc_kernel, cudaFuncAttributeMaxDynamicSharedMemorySize, SMEM_BYTES);

    dim3 gridM(4, Bq);
    modw_kernel<<<gridM, 256>>>(style, kern);

    dim3 gridC(Hq, Bq);                            // 128 rows x 8 batch = 1024 CTAs
    conv_tc_kernel<<<gridC, NTHREADS, SMEM_BYTES>>>(x, out);
}

// round 11
// speedup vs baseline: 2.0280x; 2.0280x over previous
#include <cuda_runtime.h>
#include <cstdint>

#define Bq 8
#define Hq 128
#define Wq 128
#define Cq 128
#define Fq 128

// ---------------------------------------------------------------------------
// Modulated+demodulated weights in MMA-friendly layout:
//   g_wmod[((b*9 + tap)*4 + cc)*4096 + kk*128 + f]   (kk = c%32, cc = c/32)
// Values pre-rounded to tf32 (cvt.rna).
// ---------------------------------------------------------------------------
__device__ float g_wmod[Bq * 9 * Cq * Fq];

__global__ __launch_bounds__(256) void modw_kernel(const float* __restrict__ style,
                                                   const float* __restrict__ kern)
{
    const int fg = blockIdx.x;
    const int b  = blockIdx.y;
    const int f0 = fg * 32;
    const int tid = threadIdx.x;
    const int fi = tid & 31;
    const int cp = tid >> 5;

    __shared__ float ssty[Cq];
    __shared__ float red[8][32];
    __shared__ float rr[32];

    if (tid < Cq) ssty[tid] = style[b * Cq + tid] + 1.0f;
    __syncthreads();

    float sq = 0.0f;
    for (int k = 0; k < 9; k++) {
#pragma unroll 4
        for (int j = 0; j < 16; j++) {
            int c = cp + j * 8;
            float kv = kern[(k * Cq + c) * Fq + f0 + fi] * ssty[c];
            sq += kv * kv;
        }
    }
    red[cp][fi] = sq;
    __syncthreads();
    if (tid < 32) {
        float t = 0.0f;
#pragma unroll
        for (int j = 0; j < 8; j++) t += red[j][tid];
        float xarg = t + 1e-8f;
        float r = rsqrtf(xarg);
        r = r * (1.5f - 0.5f * xarg * r * r);
        rr[tid] = r;
    }
    __syncthreads();

    for (int i = tid; i < 9 * Cq * 32; i += 256) {
        int k   = i >> 12;
        int rem = i & 4095;
        int c   = rem >> 5;
        int fl  = rem & 31;
        float v = kern[(k * Cq + c) * Fq + f0 + fl] * ssty[c] * rr[fl];
        uint32_t bits;
        asm("cvt.rna.tf32.f32 %0, %1;" : "=r"(bits) : "f"(v));
        g_wmod[(((b * 9 + k) * 4 + (c >> 5)) * 32 + (c & 31)) * Fq + f0 + fl] =
            __uint_as_float(bits);
    }
}

// ---------------------------------------------------------------------------
// Conv kernel: CTA = (b, output row h0). GEMM M=128(w) x N=128(f), K=1152.
// mma.sync.m16n8k8 tf32.  8 warps = 4(m) x 2(n), warp tile 32x64.
// x-band single-buffered (reloaded 4x with drain), ws triple-buffered ->
// one __syncthreads + one wait_group per tap.  96.75 KB smem -> 2 CTAs/SM.
// ---------------------------------------------------------------------------
#define XS_WORDS 12480                 // 3 rows * 130 pos * 32 c floats
#define WS_WORDS 4096                  // 32 k * 128 f floats
#define SMEM_WORDS (XS_WORDS + 3 * WS_WORDS)
#define SMEM_BYTES (SMEM_WORDS * 4)    // 99072

#define NTHREADS 256

__device__ __forceinline__ void cp_async16(uint32_t daddr, const void* saddr, int srcsz) {
    asm volatile("cp.async.cg.shared.global [%0], [%1], 16, %2;"
                 :: "r"(daddr), "l"(saddr), "r"(srcsz) : "memory");
}
__device__ __forceinline__ void cp_commit() {
    asm volatile("cp.async.commit_group;" ::: "memory");
}
__device__ __forceinline__ void cp_wait0() {
    asm volatile("cp.async.wait_group 0;" ::: "memory");
}

__device__ __forceinline__ void mma_tf32(float& c0, float& c1, float& c2, float& c3,
                                         uint32_t a0, uint32_t a1, uint32_t a2, uint32_t a3,
                                         uint32_t b0, uint32_t b1) {
    asm volatile("mma.sync.aligned.m16n8k8.row.col.f32.tf32.tf32.f32 "
                 "{%0,%1,%2,%3}, {%4,%5,%6,%7}, {%8,%9}, {%0,%1,%2,%3};"
                 : "+f"(c0), "+f"(c1), "+f"(c2), "+f"(c3)
                 : "r"(a0), "r"(a1), "r"(a2), "r"(a3), "r"(b0), "r"(b1));
}

__global__ __launch_bounds__(NTHREADS, 2) void conv_tc_kernel(const float* __restrict__ x,
                                                              float* __restrict__ out)
{
    extern __shared__ float sm[];
    uint32_t smbase;
    asm("{ .reg .u64 t; cvta.to.shared.u64 t, %1; cvt.u32.u64 %0, t; }"
        : "=r"(smbase) : "l"(sm));

    const int tid = threadIdx.x;
    const int lane = tid & 31;
    const int wid  = tid >> 5;
    const int g    = lane >> 2;       // groupID (0..7)
    const int tig  = lane & 3;        // thread-in-group
    const int warpM = wid & 3;        // 0..3 (m tiles of 32)
    const int warpN = wid >> 2;       // 0..1 (n tiles of 64)

    const int h0 = blockIdx.x;
    const int b  = blockIdx.y;

    float acc[2][8][4];
#pragma unroll
    for (int mt = 0; mt < 2; mt++)
#pragma unroll
        for (int nt = 0; nt < 8; nt++)
#pragma unroll
            for (int q = 0; q < 4; q++) acc[mt][nt][q] = 0.0f;

    // x band for c-chunk cc (single buffer): xs[r][p][kk], word swizzle kk ^ ((p&7)*4)
    auto fill_band = [&](int cc) {
        const float* xb = x + ((size_t)b * Hq) * Wq * Cq + cc * 32;
        for (int i = tid; i < 3 * 130 * 8; i += NTHREADS) {
            int r   = i / 1040;
            int rem = i - r * 1040;
            int p   = rem >> 3;
            int kk4 = rem & 7;
            int gh = h0 - 1 + r;
            int gw = p - 1;
            int valid = (gh >= 0 && gh < Hq && gw >= 0 && gw < Wq) ? 16 : 0;
            int ghc = gh < 0 ? 0 : (gh > Hq - 1 ? Hq - 1 : gh);
            int gwc = gw < 0 ? 0 : (gw > Wq - 1 ? Wq - 1 : gw);
            const float* src = xb + ((size_t)ghc * Wq + gwc) * Cq + kk4 * 4;
            uint32_t w = (r * 130 + p) * 32 + ((kk4 * 4) ^ ((p & 7) * 4));
            cp_async16(smbase + w * 4, src, valid);
        }
    };
    // weight slab (b,tap,cc) into ws buffer bb (of 3): ws[k][f], swizzle f ^ ((k&3)*8)
    auto fill_ws = [&](int tap, int cc, int bb) {
        const float* src0 = g_wmod + (((size_t)(b * 9 + tap) * 4 + cc)) * 4096;
        for (int i = tid; i < 1024; i += NTHREADS) {
            int kk = i >> 5;
            int f4 = i & 31;
            uint32_t w = XS_WORDS + bb * WS_WORDS + kk * 128 + ((f4 * 4) ^ ((kk & 3) * 8));
            cp_async16(smbase + w * 4, src0 + kk * 128 + f4 * 4, 16);
        }
    };

    // ---- prologue ----
    fill_band(0);
    fill_ws(0, 0, 0);
    cp_commit();

    for (int it = 0; it < 36; it++) {
        const int cc  = it / 9;
        const int tap = it - cc * 9;
        const int kh = tap / 3;
        const int kw = tap - kh * 3;

        cp_wait0();                 // data for iter it arrived (committed <= it-1)
        __syncthreads();            // all warps done reading iter it-1 buffers

        if (tap == 0 && cc > 0) {
            // band overwrite: safe, sync above drained all readers
            fill_band(cc);
            if (it + 1 < 36) fill_ws((it + 1) % 9, (it + 1) / 9, (it + 1) % 3);
            cp_commit();
            cp_wait0();             // band needed THIS iter (4x, small exposed cost)
            __syncthreads();
        } else {
            if (it + 1 < 36) fill_ws((it + 1) % 9, (it + 1) / 9, (it + 1) % 3);
            cp_commit();
        }

        const int xb = kh * 130 * 32;
        const int wb = XS_WORDS + (it % 3) * WS_WORDS;

        const int mA = warpM * 32 + g;          // mt0 rows g, g+8
        const int mB = mA + 16;                 // mt1 rows
        const int pA0 = mA + kw,  pA1 = pA0 + 8;
        const int pB0 = mB + kw,  pB1 = pB0 + 8;
        const int baseA0 = xb + pA0 * 32, mkA0 = (pA0 & 7) * 4;
        const int baseA1 = xb + pA1 * 32, mkA1 = (pA1 & 7) * 4;
        const int baseB0 = xb + pB0 * 32, mkB0 = (pB0 & 7) * 4;
        const int baseB1 = xb + pB1 * 32, mkB1 = (pB1 & 7) * 4;

#pragma unroll
        for (int ks = 0; ks < 4; ks++) {
            const int k0 = ks * 8 + tig;
            uint32_t a0[2], a1[2], a2[2], a3[2];
            a0[0] = __float_as_uint(sm[baseA0 + (k0 ^ mkA0)]);
            a2[0] = __float_as_uint(sm[baseA0 + ((k0 + 4) ^ mkA0)]);
            a1[0] = __float_as_uint(sm[baseA1 + (k0 ^ mkA1)]);
            a3[0] = __float_as_uint(sm[baseA1 + ((k0 + 4) ^ mkA1)]);
            a0[1] = __float_as_uint(sm[baseB0 + (k0 ^ mkB0)]);
            a2[1] = __float_as_uint(sm[baseB0 + ((k0 + 4) ^ mkB0)]);
            a1[1] = __float_as_uint(sm[baseB1 + (k0 ^ mkB1)]);
            a3[1] = __float_as_uint(sm[baseB1 + ((k0 + 4) ^ mkB1)]);

            const int brow = wb + k0 * 128;
#pragma unroll
            for (int nt = 0; nt < 8; nt++) {
                uint32_t bw = brow + (((warpN * 64 + nt * 8 + g) ^ (tig * 8)));
                uint32_t b0 = __float_as_uint(sm[bw]);
                uint32_t b1 = __float_as_uint(sm[bw + 512]);
                mma_tf32(acc[0][nt][0], acc[0][nt][1], acc[0][nt][2], acc[0][nt][3],
                         a0[0], a1[0], a2[0], a3[0], b0, b1);
                mma_tf32(acc[1][nt][0], acc[1][nt][1], acc[1][nt][2], acc[1][nt][3],
                         a0[1], a1[1], a2[1], a3[1], b0, b1);
            }
        }
    }

    // ---- epilogue: direct STG from accumulators ----
    float* ob = out + (((size_t)b * Hq + h0) * Wq) * Fq;
#pragma unroll
    for (int mt = 0; mt < 2; mt++) {
        const int m = warpM * 32 + mt * 16 + g;
#pragma unroll
        for (int nt = 0; nt < 8; nt++) {
            const int f = warpN * 64 + nt * 8 + tig * 2;
            float2 v0 = make_float2(acc[mt][nt][0], acc[mt][nt][1]);
            float2 v1 = make_float2(acc[mt][nt][2], acc[mt][nt][3]);
            *(float2*)(ob + (size_t)m * Fq + f) = v0;
            *(float2*)(ob + (size_t)(m + 8) * Fq + f) = v1;
        }
    }
}

// ---------------------------------------------------------------------------
extern "C" void kernel_launch(void* const* d_in, const int* in_sizes, int n_in,
                              void* d_out, int out_size)
{
    const float* x     = (const float*)d_in[0];   // (8,128,128,128) NHWC
    const float* style = (const float*)d_in[1];   // (8,128)
    const float* kern  = (const float*)d_in[2];   // (3,3,128,128)
    float* out = (float*)d_out;

    (void)in_sizes; (void)n_in; (void)out_size;

    cudaFuncSetAttribute(conv_tc_kernel, cudaFuncAttributeMaxDynamicSharedMemorySize, SMEM_BYTES);

    dim3 gridM(4, Bq);
    modw_kernel<<<gridM, 256>>>(style, kern);

    dim3 gridC(Hq, Bq);                            // 128 rows x 8 batch = 1024 CTAs
    conv_tc_kernel<<<gridC, NTHREADS, SMEM_BYTES>>>(x, out);
}